// round 4
// baseline (speedup 1.0000x reference)
#include <cuda_runtime.h>

#define M_DIM 1000
#define N_DIM 100000
#define NPB 1024            // n per block: 128 threads * 8 (two 4-wide groups)
#define MCHUNK 250          // m per block (grid.y = 4)

__device__ __forceinline__ unsigned long long pk2(float lo, float hi) {
    unsigned long long r;
    asm("mov.b64 %0, {%1, %2};" : "=l"(r) : "f"(lo), "f"(hi));
    return r;
}

__device__ __forceinline__ void fma2(unsigned long long& d,
                                     unsigned long long a,
                                     unsigned long long b,
                                     unsigned long long c) {
    asm("fma.rn.f32x2 %0, %1, %2, %3;" : "=l"(d) : "l"(a), "l"(b), "l"(c));
}

__device__ __forceinline__ void stcs4(float* p, unsigned long long a,
                                      unsigned long long b) {
    float x, y, z, w;
    asm("mov.b64 {%0, %1}, %2;" : "=f"(x), "=f"(y) : "l"(a));
    asm("mov.b64 {%0, %1}, %2;" : "=f"(z), "=f"(w) : "l"(b));
    asm volatile("st.global.cs.v4.f32 [%0], {%1, %2, %3, %4};"
                 :: "l"(p), "f"(x), "f"(y), "f"(z), "f"(w) : "memory");
}

// ---------------------------------------------------------------------------
// Fused kernel: out[m*N + n] = sum_k Z[k][m] * W[k][n]
// 128 threads/CTA, 8 n per thread (two coalesced 4-n groups 512 apart),
// 3 CTAs/SM, grid (98,4) = 392 CTAs = single wave.
// ---------------------------------------------------------------------------
__global__ void __launch_bounds__(128, 3) main_kernel(
    const float* __restrict__ phi,       // (2, N)
    const float* __restrict__ pod,       // (N, 2)
    const float* __restrict__ omega,     // (6,)
    const float* __restrict__ c_coef,    // (6,)
    const float* __restrict__ z_values,  // (6, M)
    const float* __restrict__ zsin,      // (2, M)
    const float* __restrict__ zcos,      // (2, M)
    const float* __restrict__ ztanh,     // (2, M)
    const float* __restrict__ sin_coef,  // (2,)
    const float* __restrict__ cos_coef,  // (2,)
    const float* __restrict__ tanh_coef, // (2,)
    float* __restrict__ out) {
    __shared__ float s_z[24 * MCHUNK];   // lane-duplicated Z chunk, 24 KB

    const int tid = threadIdx.x;
    const int y   = blockIdx.y;
    const int m0  = y * MCHUNK;

    // build Z chunk in shared: 12 entries per m, each duplicated into a pair
    for (int m = tid; m < MCHUNK; m += 128) {
        const int gm = m0 + m;
        float v[12];
#pragma unroll
        for (int t = 0; t < 6; t++) v[t] = c_coef[t] * z_values[t * M_DIM + gm];
        v[6]  = sin_coef[0]  * zsin[gm];
        v[7]  = sin_coef[1]  * zsin[M_DIM + gm];
        v[8]  = cos_coef[0]  * zcos[gm];
        v[9]  = cos_coef[1]  * zcos[M_DIM + gm];
        v[10] = tanh_coef[0] * ztanh[gm];
        v[11] = tanh_coef[1] * ztanh[M_DIM + gm];
#pragma unroll
        for (int k = 0; k < 12; k++) {
            s_z[m * 24 + 2 * k]     = v[k];
            s_z[m * 24 + 2 * k + 1] = v[k];
        }
    }

    // one CTA copies the third output (z_values verbatim, 6*M floats)
    if (blockIdx.x == 0 && y == 0) {
        float* ztail = out + (size_t)M_DIM * N_DIM + 2 * (size_t)N_DIM;
        for (int i = tid; i < 6 * M_DIM; i += 128) ztail[i] = z_values[i];
    }

    const int n0a = blockIdx.x * NPB + tid * 4;   // group a: always < N
    const int n0b = n0a + 512;                    // group b: may exceed N in last block
    const bool actb = (n0b < N_DIM);              // N%4==0 -> group all-in/all-out
    __syncthreads();

    const float om0 = omega[0], om1 = omega[1], om2 = omega[2];
    const float om3 = omega[3], om4 = omega[4], om5 = omega[5];

    // per-n base values for both groups (safe index for inactive b lanes)
    float ps0[8], ps1[8];
#pragma unroll
    for (int j = 0; j < 4; j++) {
        const int na = n0a + j;
        ps0[j] = phi[na]         * pod[2 * na];
        ps1[j] = phi[N_DIM + na] * pod[2 * na + 1];
        const int nb = actb ? (n0b + j) : 0;
        ps0[4 + j] = phi[nb]         * pod[2 * nb];
        ps1[4 + j] = phi[N_DIM + nb] * pod[2 * nb + 1];
    }

    // second output: latent_spatial (N,2), write once (m-chunk 0 only)
    if (y == 0) {
        float* lat = out + (size_t)M_DIM * N_DIM;
        float* la = lat + 2 * (size_t)n0a;
        *(float4*)(la)     = make_float4(ps0[0], ps1[0], ps0[1], ps1[1]);
        *(float4*)(la + 4) = make_float4(ps0[2], ps1[2], ps0[3], ps1[3]);
        if (actb) {
            float* lb = lat + 2 * (size_t)n0b;
            *(float4*)(lb)     = make_float4(ps0[4], ps1[4], ps0[5], ps1[5]);
            *(float4*)(lb + 4) = make_float4(ps0[6], ps1[6], ps0[7], ps1[7]);
        }
    }

    // W vector components k = 1..11 for all 8 n (k=0 is the constant-1 term)
    float w[12][8];
#pragma unroll
    for (int j = 0; j < 8; j++) {
        const float y0 = ps0[j], y1 = ps1[j];
        w[1][j]  = y0;
        w[2][j]  = y1;
        w[3][j]  = y0 * y0;
        w[4][j]  = y0 * y1;
        w[5][j]  = y1 * y1;
        w[6][j]  = sinf(om0 * y0);
        w[7][j]  = sinf(om3 * y1);
        w[8][j]  = cosf(om1 * y0);
        w[9][j]  = cosf(om4 * y1);
        w[10][j] = tanhf(om2 * y0);
        w[11][j] = tanhf(om5 * y1);
    }

    // pack pairs: wa=(j0,j1) wb=(j2,j3) of group a; wc,wd likewise for group b
    unsigned long long wa[11], wb[11], wc[11], wd[11];
#pragma unroll
    for (int k = 1; k < 12; k++) {
        wa[k - 1] = pk2(w[k][0], w[k][1]);
        wb[k - 1] = pk2(w[k][2], w[k][3]);
        wc[k - 1] = pk2(w[k][4], w[k][5]);
        wd[k - 1] = pk2(w[k][6], w[k][7]);
    }

    float* outA = out + (size_t)m0 * N_DIM + n0a;
    float* outB = out + (size_t)m0 * N_DIM + n0b;
    const ulonglong2* zp = (const ulonglong2*)s_z;  // 6 x ulonglong2 per m

#pragma unroll 2
    for (int mm = 0; mm < MCHUNK; mm++) {
        const ulonglong2* row = zp + mm * 6;
        const ulonglong2 z01 = row[0], z23 = row[1], z45 = row[2];
        const ulonglong2 z67 = row[3], z89 = row[4], zAB = row[5];

        // four independent 11-deep fma2 chains (k=0 term seeds each: W=1)
        unsigned long long a0 = z01.x, a1 = z01.x, b0 = z01.x, b1 = z01.x;

        fma2(a0, wa[0],  z01.y, a0);  fma2(a1, wb[0],  z01.y, a1);
        fma2(b0, wc[0],  z01.y, b0);  fma2(b1, wd[0],  z01.y, b1);
        fma2(a0, wa[1],  z23.x, a0);  fma2(a1, wb[1],  z23.x, a1);
        fma2(b0, wc[1],  z23.x, b0);  fma2(b1, wd[1],  z23.x, b1);
        fma2(a0, wa[2],  z23.y, a0);  fma2(a1, wb[2],  z23.y, a1);
        fma2(b0, wc[2],  z23.y, b0);  fma2(b1, wd[2],  z23.y, b1);
        fma2(a0, wa[3],  z45.x, a0);  fma2(a1, wb[3],  z45.x, a1);
        fma2(b0, wc[3],  z45.x, b0);  fma2(b1, wd[3],  z45.x, b1);
        fma2(a0, wa[4],  z45.y, a0);  fma2(a1, wb[4],  z45.y, a1);
        fma2(b0, wc[4],  z45.y, b0);  fma2(b1, wd[4],  z45.y, b1);
        fma2(a0, wa[5],  z67.x, a0);  fma2(a1, wb[5],  z67.x, a1);
        fma2(b0, wc[5],  z67.x, b0);  fma2(b1, wd[5],  z67.x, b1);
        fma2(a0, wa[6],  z67.y, a0);  fma2(a1, wb[6],  z67.y, a1);
        fma2(b0, wc[6],  z67.y, b0);  fma2(b1, wd[6],  z67.y, b1);
        fma2(a0, wa[7],  z89.x, a0);  fma2(a1, wb[7],  z89.x, a1);
        fma2(b0, wc[7],  z89.x, b0);  fma2(b1, wd[7],  z89.x, b1);
        fma2(a0, wa[8],  z89.y, a0);  fma2(a1, wb[8],  z89.y, a1);
        fma2(b0, wc[8],  z89.y, b0);  fma2(b1, wd[8],  z89.y, b1);
        fma2(a0, wa[9],  zAB.x, a0);  fma2(a1, wb[9],  zAB.x, a1);
        fma2(b0, wc[9],  zAB.x, b0);  fma2(b1, wd[9],  zAB.x, b1);
        fma2(a0, wa[10], zAB.y, a0);  fma2(a1, wb[10], zAB.y, a1);
        fma2(b0, wc[10], zAB.y, b0);  fma2(b1, wd[10], zAB.y, b1);

        stcs4(outA + (size_t)mm * N_DIM, a0, a1);
        if (actb) stcs4(outB + (size_t)mm * N_DIM, b0, b1);
    }
}

extern "C" void kernel_launch(void* const* d_in, const int* in_sizes, int n_in,
                              void* d_out, int out_size) {
    // metadata order:
    // 0:X 1:phi 2:POD_modes 3:c_coef 4:z_values 5:zsin 6:zcos 7:ztanh
    // 8:sin_coef 9:cos_coef 10:tanh_coef 11:omega
    const float* phi       = (const float*)d_in[1];
    const float* pod       = (const float*)d_in[2];
    const float* c_coef    = (const float*)d_in[3];
    const float* z_values  = (const float*)d_in[4];
    const float* zsin      = (const float*)d_in[5];
    const float* zcos      = (const float*)d_in[6];
    const float* ztanh     = (const float*)d_in[7];
    const float* sin_coef  = (const float*)d_in[8];
    const float* cos_coef  = (const float*)d_in[9];
    const float* tanh_coef = (const float*)d_in[10];
    const float* omega     = (const float*)d_in[11];

    float* out = (float*)d_out;

    dim3 grid((N_DIM + NPB - 1) / NPB, M_DIM / MCHUNK);  // (98, 4) = 392 CTAs
    main_kernel<<<grid, 128>>>(phi, pod, omega, c_coef, z_values, zsin, zcos,
                               ztanh, sin_coef, cos_coef, tanh_coef, out);
}